// round 5
// baseline (speedup 1.0000x reference)
#include <cuda_runtime.h>
#include <math.h>

// Problem constants
#define Bn   32
#define Cn   16
#define HWn  65536
#define T1   128               // tiles per batch, pass1 (512 px/tile)
#define T3   128               // tiles per batch, pass3 (512 px/tile)
#define PPB  512               // pixels per block
#define THR1 256               // pass1: 2 threads per pixel-quad (8 ch each)
#define THR3 128               // pass3: 4 px/thread, streamed channels

// Scratch (__device__ globals; fully overwritten each run)
__device__ float g_part[2][Bn][32][T1];   // [tensor][batch][slot:0-15 tot,16-31 cls0][tile]
__device__ float g_cnt[Bn][T1];           // class-0 count partials (written by z==0)
__device__ float g_dm[2][Bn][Cn];         // normalized mean difference vectors
__device__ float g_msep[Bn * T3];         // per-block MSE partials
__device__ unsigned int g_done;           // last-block counter (self-resetting)

__device__ __forceinline__ float wred(float v) {
    v += __shfl_down_sync(0xFFFFFFFFu, v, 16);
    v += __shfl_down_sync(0xFFFFFFFFu, v, 8);
    v += __shfl_down_sync(0xFFFFFFFFu, v, 4);
    v += __shfl_down_sync(0xFFFFFFFFu, v, 2);
    v += __shfl_down_sync(0xFFFFFFFFu, v, 1);
    return v;
}
// Parity-preserving reduce: lane0 ends with sum over even lanes, lane1 over odd.
__device__ __forceinline__ float wred2(float v) {
    v += __shfl_down_sync(0xFFFFFFFFu, v, 16);
    v += __shfl_down_sync(0xFFFFFFFFu, v, 8);
    v += __shfl_down_sync(0xFFFFFFFFu, v, 4);
    v += __shfl_down_sync(0xFFFFFFFFu, v, 2);
    return v;
}
__device__ __forceinline__ double wredd(double v) {
    v += __shfl_down_sync(0xFFFFFFFFu, v, 16);
    v += __shfl_down_sync(0xFFFFFFFFu, v, 8);
    v += __shfl_down_sync(0xFFFFFFFFu, v, 4);
    v += __shfl_down_sync(0xFFFFFFFFu, v, 2);
    v += __shfl_down_sync(0xFFFFFFFFu, v, 1);
    return v;
}

// Per-block dtype sniff: int64 targets with values in {0,1} have all odd
// 32-bit words zero; int32 targets have random labels there. All blocks read
// the same 512 words (L2-broadcast) -> identical deterministic result.
__device__ __forceinline__ int sniff_is32(const int* __restrict__ tw, int tid, int nthr) {
    int any = 0;
    for (int i = tid; i < 512; i += nthr) any |= tw[2 * i + 1];
    return __syncthreads_or(any);
}

__device__ __forceinline__ void load_cls4(const int* __restrict__ twb, int p, int is32,
                                          int& c0, int& c1, int& c2, int& c3) {
    if (is32) {
        int4 v = *(const int4*)(twb + p);
        c0 = v.x; c1 = v.y; c2 = v.z; c3 = v.w;
    } else {
        int4 a = *(const int4*)(twb + 2 * p);
        int4 b = *(const int4*)(twb + 2 * p + 4);
        c0 = a.x; c1 = a.z; c2 = b.x; c3 = b.z;
    }
}

// ---------------------------------------------------------------------------
// Pass 1: per-(tensor,batch,tile) partial sums of L2-normalized features.
// grid (T1, Bn, 2); 256 thr; thread pair shares a pixel-quad, 8 channels each.
// ---------------------------------------------------------------------------
__global__ void __launch_bounds__(THR1, 4)
pass1_kernel(const float* __restrict__ S, const float* __restrict__ T,
             const int* __restrict__ TW) {
    const int tile = blockIdx.x, b = blockIdx.y, z = blockIdx.z;
    const int tid  = threadIdx.x;
    const int is32 = sniff_is32(TW, tid, THR1);

    const int half = tid & 1;            // 0: channels 0-7, 1: channels 8-15
    const int q    = tid >> 1;           // pixel-quad index in block

    const float* Xb  = (z ? T : S) + ((size_t)b << 20);
    const int*   twb = TW + (is32 ? ((size_t)b << 16) : ((size_t)b << 17));

    const int p = tile * PPB + q * 4;
    int c0, c1, c2, c3;
    load_cls4(twb, p, is32, c0, c1, c2, c3);
    const float m0 = (c0 == 0) ? 1.f : 0.f;
    const float m1 = (c1 == 0) ? 1.f : 0.f;
    const float m2 = (c2 == 0) ? 1.f : 0.f;
    const float m3 = (c3 == 0) ? 1.f : 0.f;
    float cnt = (half == 0) ? ((m0 + m1) + (m2 + m3)) : 0.f;

    const float* base = Xb + ((size_t)(half * 8) << 16) + p;
    float4 v[8];
#pragma unroll
    for (int c = 0; c < 8; c++) v[c] = *(const float4*)(base + ((size_t)c << 16));

    // Partial norms over 8 channels, completed across the pair via shfl_xor.
    float n0 = 0.f, n1 = 0.f, n2 = 0.f, n3 = 0.f;
#pragma unroll
    for (int c = 0; c < 8; c++) {
        n0 = fmaf(v[c].x, v[c].x, n0); n1 = fmaf(v[c].y, v[c].y, n1);
        n2 = fmaf(v[c].z, v[c].z, n2); n3 = fmaf(v[c].w, v[c].w, n3);
    }
    n0 += __shfl_xor_sync(0xFFFFFFFFu, n0, 1);
    n1 += __shfl_xor_sync(0xFFFFFFFFu, n1, 1);
    n2 += __shfl_xor_sync(0xFFFFFFFFu, n2, 1);
    n3 += __shfl_xor_sync(0xFFFFFFFFu, n3, 1);
    const float i0 = rsqrtf(fmaxf(n0, 1e-24f));
    const float i1 = rsqrtf(fmaxf(n1, 1e-24f));
    const float i2 = rsqrtf(fmaxf(n2, 1e-24f));
    const float i3 = rsqrtf(fmaxf(n3, 1e-24f));

    float at[8], a0[8];
#pragma unroll
    for (int c = 0; c < 8; c++) {
        const float f0 = v[c].x * i0, f1 = v[c].y * i1;
        const float f2 = v[c].z * i2, f3 = v[c].w * i3;
        at[c] = (f0 + f1) + (f2 + f3);
        a0[c] = (m0 * f0 + m1 * f1) + (m2 * f2 + m3 * f3);
    }

    // Parity-preserving warp reduce: lane0 holds channels 0-7, lane1 8-15.
    __shared__ float sred[THR1 / 32][33];
    const int lane = tid & 31, w = tid >> 5;
#pragma unroll
    for (int c = 0; c < 8; c++) { at[c] = wred2(at[c]); a0[c] = wred2(a0[c]); }
    cnt = wred2(cnt);
    if (lane < 2) {
#pragma unroll
        for (int c = 0; c < 8; c++) {
            sred[w][lane * 8 + c]      = at[c];
            sred[w][16 + lane * 8 + c] = a0[c];
        }
        if (lane == 0) sred[w][32] = cnt;
    }
    __syncthreads();
    if (tid < 33) {
        float s = 0.f;
#pragma unroll
        for (int ww = 0; ww < THR1 / 32; ww++) s += sred[ww][tid];
        if (tid < 32)      g_part[z][b][tid][tile] = s;
        else if (z == 0)   g_cnt[b][tile] = s;
    }
}

// ---------------------------------------------------------------------------
// Finalize: reduce tile partials -> normalized mean-difference vectors dM.
// grid (Bn, 2), 256 threads.
// ---------------------------------------------------------------------------
__global__ void finalize_kernel() {
    const int b = blockIdx.x, z = blockIdx.y;
    const int tid = threadIdx.x;

    __shared__ float s[8][32];
    __shared__ float sc[8];
    __shared__ float red[32];
    __shared__ float scnt;
    __shared__ float smean[2][Cn];
    __shared__ float srn[2];

    {   // 256 threads = 32 slots x 8 groups of 16 tiles
        const int slot = tid & 31, g = tid >> 5;
        const float* base = &g_part[z][b][slot][0] + g * 16;
        float a = 0.f;
#pragma unroll
        for (int k = 0; k < 4; k++) {
            const float4 v = *(const float4*)(base + 4 * k);
            a += (v.x + v.y) + (v.z + v.w);
        }
        s[g][slot] = a;
    }
    if (tid < 8) {
        const float* cb = &g_cnt[b][0] + tid * 16;
        float a = 0.f;
#pragma unroll
        for (int k = 0; k < 4; k++) {
            const float4 v = *(const float4*)(cb + 4 * k);
            a += (v.x + v.y) + (v.z + v.w);
        }
        sc[tid] = a;
    }
    __syncthreads();
    if (tid < 32) {
        float a = 0.f;
#pragma unroll
        for (int g = 0; g < 8; g++) a += s[g][tid];
        red[tid] = a;
    } else if (tid == 32) {
        float a = 0.f;
#pragma unroll
        for (int g = 0; g < 8; g++) a += sc[g];
        scnt = a;
    }
    __syncthreads();
    if (tid < 2) {
        const int cls = tid;
        const float cnt0 = scnt;
        const float cnt  = cls ? ((float)HWn - cnt0) : cnt0;
        const float inv  = 1.0f / (cnt + 1e-6f);
        float nm2 = 0.f;
#pragma unroll
        for (int c = 0; c < Cn; c++) {
            const float tot = red[c], s0 = red[16 + c];
            const float sv  = cls ? (tot - s0) : s0;
            const float m   = sv * inv;
            smean[cls][c] = m;
            nm2 = fmaf(m, m, nm2);
        }
        srn[cls] = 1.0f / fmaxf(sqrtf(nm2), 1e-8f);
    }
    __syncthreads();
    if (tid < Cn) {
        g_dm[z][b][tid] = smean[0][tid] * srn[0] - smean[1][tid] * srn[1];
    }
}

// ---------------------------------------------------------------------------
// Pass 3: cd = dot(v, dM) * rsqrt(||v||^2); pcsim = exp(+-cd); MSE.
// grid (T3, Bn); 4 px/thread, float4 loads, channels streamed.
// ---------------------------------------------------------------------------
__global__ void __launch_bounds__(THR3, 10)
pass3_kernel(const float* __restrict__ S, const float* __restrict__ T,
             const int* __restrict__ TW, float* __restrict__ out) {
    const int tile = blockIdx.x, b = blockIdx.y;
    const int tid  = threadIdx.x;
    const int is32 = sniff_is32(TW, tid, THR3);

    __shared__ float sdM[2][Cn];
    __shared__ unsigned int slast;
    if (tid < 32) {
        const int z = tid >> 4, c = tid & 15;
        sdM[z][c] = g_dm[z][b][c];
    }
    __syncthreads();

    const float* Sb  = S + ((size_t)b << 20);
    const float* Tb  = T + ((size_t)b << 20);
    const int*   twb = TW + (is32 ? ((size_t)b << 16) : ((size_t)b << 17));

    const int p = tile * PPB + tid * 4;
    int c0, c1, c2, c3;
    load_cls4(twb, p, is32, c0, c1, c2, c3);
    const float s0 = (c0 == 0) ? 1.f : -1.f;
    const float s1 = (c1 == 0) ? 1.f : -1.f;
    const float s2 = (c2 == 0) ? 1.f : -1.f;
    const float s3 = (c3 == 0) ? 1.f : -1.f;

    float pcS0, pcS1, pcS2, pcS3;
    {   // ---- S ----
        float n0 = 0.f, n1 = 0.f, n2 = 0.f, n3 = 0.f;
        float d0 = 0.f, d1 = 0.f, d2 = 0.f, d3 = 0.f;
#pragma unroll
        for (int c = 0; c < Cn; c++) {
            const float4 v = *(const float4*)(Sb + ((size_t)c << 16) + p);
            const float m = sdM[0][c];
            n0 = fmaf(v.x, v.x, n0); n1 = fmaf(v.y, v.y, n1);
            n2 = fmaf(v.z, v.z, n2); n3 = fmaf(v.w, v.w, n3);
            d0 = fmaf(v.x, m, d0); d1 = fmaf(v.y, m, d1);
            d2 = fmaf(v.z, m, d2); d3 = fmaf(v.w, m, d3);
        }
        pcS0 = __expf(s0 * d0 * rsqrtf(fmaxf(n0, 1e-24f)));
        pcS1 = __expf(s1 * d1 * rsqrtf(fmaxf(n1, 1e-24f)));
        pcS2 = __expf(s2 * d2 * rsqrtf(fmaxf(n2, 1e-24f)));
        pcS3 = __expf(s3 * d3 * rsqrtf(fmaxf(n3, 1e-24f)));
    }
    float acc;
    {   // ---- T ----
        float n0 = 0.f, n1 = 0.f, n2 = 0.f, n3 = 0.f;
        float d0 = 0.f, d1 = 0.f, d2 = 0.f, d3 = 0.f;
#pragma unroll
        for (int c = 0; c < Cn; c++) {
            const float4 v = *(const float4*)(Tb + ((size_t)c << 16) + p);
            const float m = sdM[1][c];
            n0 = fmaf(v.x, v.x, n0); n1 = fmaf(v.y, v.y, n1);
            n2 = fmaf(v.z, v.z, n2); n3 = fmaf(v.w, v.w, n3);
            d0 = fmaf(v.x, m, d0); d1 = fmaf(v.y, m, d1);
            d2 = fmaf(v.z, m, d2); d3 = fmaf(v.w, m, d3);
        }
        const float e0 = pcS0 - __expf(s0 * d0 * rsqrtf(fmaxf(n0, 1e-24f)));
        const float e1 = pcS1 - __expf(s1 * d1 * rsqrtf(fmaxf(n1, 1e-24f)));
        const float e2 = pcS2 - __expf(s2 * d2 * rsqrtf(fmaxf(n2, 1e-24f)));
        const float e3 = pcS3 - __expf(s3 * d3 * rsqrtf(fmaxf(n3, 1e-24f)));
        acc = fmaf(e0, e0, e1 * e1) + fmaf(e2, e2, e3 * e3);
    }

    // Block reduce MSE partial, then last-block final reduction.
    __shared__ float smse[THR3 / 32];
    acc = wred(acc);
    const int lane = tid & 31, w = tid >> 5;
    if (lane == 0) smse[w] = acc;
    __syncthreads();
    const int gid = b * T3 + tile;
    if (tid == 0) {
        float sv = 0.f;
#pragma unroll
        for (int ww = 0; ww < THR3 / 32; ww++) sv += smse[ww];
        g_msep[gid] = sv;
        __threadfence();
        const unsigned int old = atomicAdd(&g_done, 1u);
        slast = (old == (unsigned int)(Bn * T3 - 1)) ? 1u : 0u;
    }
    __syncthreads();

    if (slast) {
        volatile float* mp = &g_msep[0];
        double d = 0.0;
#pragma unroll
        for (int k = 0; k < (Bn * T3) / THR3; k++)
            d += (double)mp[tid * ((Bn * T3) / THR3) + k];
        d = wredd(d);
        __shared__ double sd[THR3 / 32];
        if (lane == 0) sd[w] = d;
        __syncthreads();
        if (tid == 0) {
            double tot = 0.0;
#pragma unroll
            for (int ww = 0; ww < THR3 / 32; ww++) tot += sd[ww];
            out[0] = (float)(tot * (1.0 / ((double)Bn * (double)HWn)));
            g_done = 0;   // reset for next graph replay
        }
    }
}

extern "C" void kernel_launch(void* const* d_in, const int* in_sizes, int n_in,
                              void* d_out, int out_size) {
    const float* S  = (const float*)d_in[0];
    const float* T  = (const float*)d_in[1];
    const int*   TW = (const int*)d_in[2];
    float* out = (float*)d_out;

    dim3 g1(T1, Bn, 2);
    pass1_kernel<<<g1, THR1>>>(S, T, TW);
    dim3 gf(Bn, 2);
    finalize_kernel<<<gf, 256>>>();
    dim3 g3(T3, Bn);
    pass3_kernel<<<g3, THR3>>>(S, T, TW, out);
}

// round 6
// speedup vs baseline: 1.0619x; 1.0619x over previous
#include <cuda_runtime.h>
#include <math.h>

// Problem constants
#define Bn   32
#define Cn   16
#define HWn  65536
#define T1   128               // tiles per batch, pass1 (512 px/tile)
#define T3   128               // tiles per batch, pass3 (512 px/tile)
#define PPB  512               // pixels per block
#define THR  128               // threads per block; 4 px/thread, float4

// Scratch (__device__ globals; fully overwritten each run)
__device__ float g_part[2][Bn][32][T1];   // [tensor][batch][slot:0-15 tot,16-31 cls0][tile]
__device__ float g_cnt[Bn][T1];           // class-0 count partials (written by z==0)
__device__ float g_dm[2][Bn][Cn];         // normalized mean difference vectors
__device__ float g_msep[Bn * T3];         // per-block MSE partials
__device__ unsigned int g_done;           // last-block counter (self-resetting)

__device__ __forceinline__ float wred(float v) {
    v += __shfl_down_sync(0xFFFFFFFFu, v, 16);
    v += __shfl_down_sync(0xFFFFFFFFu, v, 8);
    v += __shfl_down_sync(0xFFFFFFFFu, v, 4);
    v += __shfl_down_sync(0xFFFFFFFFu, v, 2);
    v += __shfl_down_sync(0xFFFFFFFFu, v, 1);
    return v;
}
__device__ __forceinline__ double wredd(double v) {
    v += __shfl_down_sync(0xFFFFFFFFu, v, 16);
    v += __shfl_down_sync(0xFFFFFFFFu, v, 8);
    v += __shfl_down_sync(0xFFFFFFFFu, v, 4);
    v += __shfl_down_sync(0xFFFFFFFFu, v, 2);
    v += __shfl_down_sync(0xFFFFFFFFu, v, 1);
    return v;
}

// Per-block dtype sniff: int64 targets with values in {0,1} have all odd
// 32-bit words zero; int32 targets have random labels there. All blocks read
// the same 512 words (L2-broadcast) -> identical deterministic result.
__device__ __forceinline__ int sniff_is32(const int* __restrict__ tw, int tid) {
    int any = 0;
#pragma unroll
    for (int i = tid; i < 512; i += THR) any |= tw[2 * i + 1];
    return __syncthreads_or(any);
}

__device__ __forceinline__ void load_cls4(const int* __restrict__ twb, int p, int is32,
                                          int& c0, int& c1, int& c2, int& c3) {
    if (is32) {
        int4 v = *(const int4*)(twb + p);
        c0 = v.x; c1 = v.y; c2 = v.z; c3 = v.w;
    } else {
        int4 a = *(const int4*)(twb + 2 * p);
        int4 b = *(const int4*)(twb + 2 * p + 4);
        c0 = a.x; c1 = a.z; c2 = b.x; c3 = b.z;
    }
}

// ---------------------------------------------------------------------------
// Pass 1: per-(tensor,batch,tile) partial sums of L2-normalized features.
// grid (T1, Bn, 2); 4 px/thread, float4 loads, tile held in registers. (R4)
// ---------------------------------------------------------------------------
__global__ void __launch_bounds__(THR, 4)
pass1_kernel(const float* __restrict__ S, const float* __restrict__ T,
             const int* __restrict__ TW) {
    const int tile = blockIdx.x, b = blockIdx.y, z = blockIdx.z;
    const int tid  = threadIdx.x;
    const int is32 = sniff_is32(TW, tid);

    const float* Xb  = (z ? T : S) + ((size_t)b << 20);
    const int*   twb = TW + (is32 ? ((size_t)b << 16) : ((size_t)b << 17));

    const int p = tile * PPB + tid * 4;
    int c0, c1, c2, c3;
    load_cls4(twb, p, is32, c0, c1, c2, c3);
    const float m0 = (c0 == 0) ? 1.f : 0.f;
    const float m1 = (c1 == 0) ? 1.f : 0.f;
    const float m2 = (c2 == 0) ? 1.f : 0.f;
    const float m3 = (c3 == 0) ? 1.f : 0.f;
    float cnt = (m0 + m1) + (m2 + m3);

    float4 v[Cn];
#pragma unroll
    for (int c = 0; c < Cn; c++) v[c] = *(const float4*)(Xb + ((size_t)c << 16) + p);

    float n0 = 0.f, n1 = 0.f, n2 = 0.f, n3 = 0.f;
#pragma unroll
    for (int c = 0; c < Cn; c++) {
        n0 = fmaf(v[c].x, v[c].x, n0); n1 = fmaf(v[c].y, v[c].y, n1);
        n2 = fmaf(v[c].z, v[c].z, n2); n3 = fmaf(v[c].w, v[c].w, n3);
    }
    const float i0 = rsqrtf(fmaxf(n0, 1e-24f));
    const float i1 = rsqrtf(fmaxf(n1, 1e-24f));
    const float i2 = rsqrtf(fmaxf(n2, 1e-24f));
    const float i3 = rsqrtf(fmaxf(n3, 1e-24f));

    float at[Cn], a0[Cn];
#pragma unroll
    for (int c = 0; c < Cn; c++) {
        const float f0 = v[c].x * i0, f1 = v[c].y * i1;
        const float f2 = v[c].z * i2, f3 = v[c].w * i3;
        at[c] = (f0 + f1) + (f2 + f3);
        a0[c] = (m0 * f0 + m1 * f1) + (m2 * f2 + m3 * f3);
    }

    // Block reduce 33 slots; write partials (no atomics).
    __shared__ float sred[THR / 32][33];
    const int lane = tid & 31, w = tid >> 5;
#pragma unroll
    for (int c = 0; c < Cn; c++) { at[c] = wred(at[c]); a0[c] = wred(a0[c]); }
    cnt = wred(cnt);
    if (lane == 0) {
#pragma unroll
        for (int c = 0; c < Cn; c++) { sred[w][c] = at[c]; sred[w][16 + c] = a0[c]; }
        sred[w][32] = cnt;
    }
    __syncthreads();
    if (tid < 33) {
        float s = 0.f;
#pragma unroll
        for (int ww = 0; ww < THR / 32; ww++) s += sred[ww][tid];
        if (tid < 32)      g_part[z][b][tid][tile] = s;
        else if (z == 0)   g_cnt[b][tile] = s;
    }
}

// ---------------------------------------------------------------------------
// Finalize: reduce tile partials -> normalized mean-difference vectors dM.
// grid (Bn, 2), 256 threads.
// ---------------------------------------------------------------------------
__global__ void finalize_kernel() {
    const int b = blockIdx.x, z = blockIdx.y;
    const int tid = threadIdx.x;

    __shared__ float s[8][32];
    __shared__ float sc[8];
    __shared__ float red[32];
    __shared__ float scnt;
    __shared__ float smean[2][Cn];
    __shared__ float srn[2];

    {   // 256 threads = 32 slots x 8 groups of 16 tiles
        const int slot = tid & 31, g = tid >> 5;
        const float* base = &g_part[z][b][slot][0] + g * 16;
        float a = 0.f;
#pragma unroll
        for (int k = 0; k < 4; k++) {
            const float4 v = *(const float4*)(base + 4 * k);
            a += (v.x + v.y) + (v.z + v.w);
        }
        s[g][slot] = a;
    }
    if (tid < 8) {
        const float* cb = &g_cnt[b][0] + tid * 16;
        float a = 0.f;
#pragma unroll
        for (int k = 0; k < 4; k++) {
            const float4 v = *(const float4*)(cb + 4 * k);
            a += (v.x + v.y) + (v.z + v.w);
        }
        sc[tid] = a;
    }
    __syncthreads();
    if (tid < 32) {
        float a = 0.f;
#pragma unroll
        for (int g = 0; g < 8; g++) a += s[g][tid];
        red[tid] = a;
    } else if (tid == 32) {
        float a = 0.f;
#pragma unroll
        for (int g = 0; g < 8; g++) a += sc[g];
        scnt = a;
    }
    __syncthreads();
    if (tid < 2) {
        const int cls = tid;
        const float cnt0 = scnt;
        const float cnt  = cls ? ((float)HWn - cnt0) : cnt0;
        const float inv  = 1.0f / (cnt + 1e-6f);
        float nm2 = 0.f;
#pragma unroll
        for (int c = 0; c < Cn; c++) {
            const float tot = red[c], s0 = red[16 + c];
            const float sv  = cls ? (tot - s0) : s0;
            const float m   = sv * inv;
            smean[cls][c] = m;
            nm2 = fmaf(m, m, nm2);
        }
        srn[cls] = 1.0f / fmaxf(sqrtf(nm2), 1e-8f);
    }
    __syncthreads();
    if (tid < Cn) {
        g_dm[z][b][tid] = smean[0][tid] * srn[0] - smean[1][tid] * srn[1];
    }
}

// ---------------------------------------------------------------------------
// Pass 3: cd = dot(v, dM) * rsqrt(||v||^2); pcsim = exp(+-cd); MSE.
// grid (T3, Bn); 4 px/thread, float4 loads, channels streamed.
// ---------------------------------------------------------------------------
__global__ void __launch_bounds__(THR, 10)
pass3_kernel(const float* __restrict__ S, const float* __restrict__ T,
             const int* __restrict__ TW, float* __restrict__ out) {
    const int tile = blockIdx.x, b = blockIdx.y;
    const int tid  = threadIdx.x;
    const int is32 = sniff_is32(TW, tid);

    __shared__ float sdM[2][Cn];
    __shared__ unsigned int slast;
    if (tid < 32) {
        const int z = tid >> 4, c = tid & 15;
        sdM[z][c] = g_dm[z][b][c];
    }
    __syncthreads();

    const float* Sb  = S + ((size_t)b << 20);
    const float* Tb  = T + ((size_t)b << 20);
    const int*   twb = TW + (is32 ? ((size_t)b << 16) : ((size_t)b << 17));

    const int p = tile * PPB + tid * 4;
    int c0, c1, c2, c3;
    load_cls4(twb, p, is32, c0, c1, c2, c3);
    const float s0 = (c0 == 0) ? 1.f : -1.f;
    const float s1 = (c1 == 0) ? 1.f : -1.f;
    const float s2 = (c2 == 0) ? 1.f : -1.f;
    const float s3 = (c3 == 0) ? 1.f : -1.f;

    float pcS0, pcS1, pcS2, pcS3;
    {   // ---- S ----
        float n0 = 0.f, n1 = 0.f, n2 = 0.f, n3 = 0.f;
        float d0 = 0.f, d1 = 0.f, d2 = 0.f, d3 = 0.f;
#pragma unroll
        for (int c = 0; c < Cn; c++) {
            const float4 v = *(const float4*)(Sb + ((size_t)c << 16) + p);
            const float m = sdM[0][c];
            n0 = fmaf(v.x, v.x, n0); n1 = fmaf(v.y, v.y, n1);
            n2 = fmaf(v.z, v.z, n2); n3 = fmaf(v.w, v.w, n3);
            d0 = fmaf(v.x, m, d0); d1 = fmaf(v.y, m, d1);
            d2 = fmaf(v.z, m, d2); d3 = fmaf(v.w, m, d3);
        }
        pcS0 = __expf(s0 * d0 * rsqrtf(fmaxf(n0, 1e-24f)));
        pcS1 = __expf(s1 * d1 * rsqrtf(fmaxf(n1, 1e-24f)));
        pcS2 = __expf(s2 * d2 * rsqrtf(fmaxf(n2, 1e-24f)));
        pcS3 = __expf(s3 * d3 * rsqrtf(fmaxf(n3, 1e-24f)));
    }
    float acc;
    {   // ---- T ----
        float n0 = 0.f, n1 = 0.f, n2 = 0.f, n3 = 0.f;
        float d0 = 0.f, d1 = 0.f, d2 = 0.f, d3 = 0.f;
#pragma unroll
        for (int c = 0; c < Cn; c++) {
            const float4 v = *(const float4*)(Tb + ((size_t)c << 16) + p);
            const float m = sdM[1][c];
            n0 = fmaf(v.x, v.x, n0); n1 = fmaf(v.y, v.y, n1);
            n2 = fmaf(v.z, v.z, n2); n3 = fmaf(v.w, v.w, n3);
            d0 = fmaf(v.x, m, d0); d1 = fmaf(v.y, m, d1);
            d2 = fmaf(v.z, m, d2); d3 = fmaf(v.w, m, d3);
        }
        const float e0 = pcS0 - __expf(s0 * d0 * rsqrtf(fmaxf(n0, 1e-24f)));
        const float e1 = pcS1 - __expf(s1 * d1 * rsqrtf(fmaxf(n1, 1e-24f)));
        const float e2 = pcS2 - __expf(s2 * d2 * rsqrtf(fmaxf(n2, 1e-24f)));
        const float e3 = pcS3 - __expf(s3 * d3 * rsqrtf(fmaxf(n3, 1e-24f)));
        acc = fmaf(e0, e0, e1 * e1) + fmaf(e2, e2, e3 * e3);
    }

    // Block reduce MSE partial, then last-block final reduction.
    __shared__ float smse[THR / 32];
    acc = wred(acc);
    const int lane = tid & 31, w = tid >> 5;
    if (lane == 0) smse[w] = acc;
    __syncthreads();
    const int gid = b * T3 + tile;
    if (tid == 0) {
        float sv = 0.f;
#pragma unroll
        for (int ww = 0; ww < THR / 32; ww++) sv += smse[ww];
        g_msep[gid] = sv;
        __threadfence();
        const unsigned int old = atomicAdd(&g_done, 1u);
        slast = (old == (unsigned int)(Bn * T3 - 1)) ? 1u : 0u;
    }
    __syncthreads();

    if (slast) {
        volatile float* mp = &g_msep[0];
        double d = 0.0;
#pragma unroll
        for (int k = 0; k < (Bn * T3) / THR; k++)
            d += (double)mp[tid * ((Bn * T3) / THR) + k];
        d = wredd(d);
        __shared__ double sd[THR / 32];
        if (lane == 0) sd[w] = d;
        __syncthreads();
        if (tid == 0) {
            double tot = 0.0;
#pragma unroll
            for (int ww = 0; ww < THR / 32; ww++) tot += sd[ww];
            out[0] = (float)(tot * (1.0 / ((double)Bn * (double)HWn)));
            g_done = 0;   // reset for next graph replay
        }
    }
}

extern "C" void kernel_launch(void* const* d_in, const int* in_sizes, int n_in,
                              void* d_out, int out_size) {
    const float* S  = (const float*)d_in[0];
    const float* T  = (const float*)d_in[1];
    const int*   TW = (const int*)d_in[2];
    float* out = (float*)d_out;

    dim3 g1(T1, Bn, 2);
    pass1_kernel<<<g1, THR>>>(S, T, TW);
    dim3 gf(Bn, 2);
    finalize_kernel<<<gf, 256>>>();
    dim3 g3(T3, Bn);
    pass3_kernel<<<g3, THR>>>(S, T, TW, out);
}

// round 7
// speedup vs baseline: 1.0622x; 1.0003x over previous
#include <cuda_runtime.h>
#include <math.h>

// Problem constants
#define Bn   32
#define Cn   16
#define HWn  65536
#define T1   64                // tiles per batch, pass1 (1024 px/tile, 2 quad-iters)
#define T3   128               // tiles per batch, pass3 (512 px/tile)
#define PPB1 1024
#define PPB3 512
#define THR  128               // threads per block

// Scratch (__device__ globals; fully overwritten each run)
__device__ float g_part[2][Bn][32][T1];   // [tensor][batch][slot:0-15 tot,16-31 cls0][tile]
__device__ float g_cnt[Bn][T1];           // class-0 count partials (written by z==0)
__device__ float g_dm[2][Bn][Cn];         // normalized mean difference vectors
__device__ float g_msep[Bn * T3];         // per-block MSE partials
__device__ unsigned int g_done;           // last-block counter (self-resetting)

__device__ __forceinline__ float wred(float v) {
    v += __shfl_down_sync(0xFFFFFFFFu, v, 16);
    v += __shfl_down_sync(0xFFFFFFFFu, v, 8);
    v += __shfl_down_sync(0xFFFFFFFFu, v, 4);
    v += __shfl_down_sync(0xFFFFFFFFu, v, 2);
    v += __shfl_down_sync(0xFFFFFFFFu, v, 1);
    return v;
}
__device__ __forceinline__ double wredd(double v) {
    v += __shfl_down_sync(0xFFFFFFFFu, v, 16);
    v += __shfl_down_sync(0xFFFFFFFFu, v, 8);
    v += __shfl_down_sync(0xFFFFFFFFu, v, 4);
    v += __shfl_down_sync(0xFFFFFFFFu, v, 2);
    v += __shfl_down_sync(0xFFFFFFFFu, v, 1);
    return v;
}

__device__ __forceinline__ float4 ldcs4(const float* p) {
    return __ldcs((const float4*)p);
}

// Per-block dtype sniff: int64 targets with values in {0,1} have all odd
// 32-bit words zero; int32 targets have random labels there. All blocks read
// the same 512 words (L2-broadcast) -> identical deterministic result.
__device__ __forceinline__ int sniff_is32(const int* __restrict__ tw, int tid) {
    int any = 0;
#pragma unroll
    for (int i = tid; i < 512; i += THR) any |= tw[2 * i + 1];
    return __syncthreads_or(any);
}

__device__ __forceinline__ void load_cls4(const int* __restrict__ twb, int p, int is32,
                                          int& c0, int& c1, int& c2, int& c3) {
    if (is32) {
        int4 v = __ldcs((const int4*)(twb + p));
        c0 = v.x; c1 = v.y; c2 = v.z; c3 = v.w;
    } else {
        int4 a = __ldcs((const int4*)(twb + 2 * p));
        int4 b = __ldcs((const int4*)(twb + 2 * p + 4));
        c0 = a.x; c1 = a.z; c2 = b.x; c3 = b.z;
    }
}

// ---------------------------------------------------------------------------
// Pass 1: per-(tensor,batch,tile) partial sums of L2-normalized features.
// grid (T1, Bn, 2); 2 quad-iterations/thread (8 px), float4 loads.
// ---------------------------------------------------------------------------
__global__ void __launch_bounds__(THR, 5)
pass1_kernel(const float* __restrict__ S, const float* __restrict__ T,
             const int* __restrict__ TW) {
    const int tile = blockIdx.x, b = blockIdx.y, z = blockIdx.z;
    const int tid  = threadIdx.x;
    const int is32 = sniff_is32(TW, tid);

    const float* Xb  = (z ? T : S) + ((size_t)b << 20);
    const int*   twb = TW + (is32 ? ((size_t)b << 16) : ((size_t)b << 17));

    float at[Cn], a0[Cn];
#pragma unroll
    for (int c = 0; c < Cn; c++) { at[c] = 0.f; a0[c] = 0.f; }
    float cnt = 0.f;

#pragma unroll
    for (int it = 0; it < 2; ++it) {
        const int p = tile * PPB1 + it * (THR * 4) + tid * 4;

        int c0, c1, c2, c3;
        load_cls4(twb, p, is32, c0, c1, c2, c3);
        const float m0 = (c0 == 0) ? 1.f : 0.f;
        const float m1 = (c1 == 0) ? 1.f : 0.f;
        const float m2 = (c2 == 0) ? 1.f : 0.f;
        const float m3 = (c3 == 0) ? 1.f : 0.f;
        cnt += (m0 + m1) + (m2 + m3);

        float4 v[Cn];
#pragma unroll
        for (int c = 0; c < Cn; c++) v[c] = ldcs4(Xb + ((size_t)c << 16) + p);

        float n0 = 0.f, n1 = 0.f, n2 = 0.f, n3 = 0.f;
#pragma unroll
        for (int c = 0; c < Cn; c++) {
            n0 = fmaf(v[c].x, v[c].x, n0); n1 = fmaf(v[c].y, v[c].y, n1);
            n2 = fmaf(v[c].z, v[c].z, n2); n3 = fmaf(v[c].w, v[c].w, n3);
        }
        const float i0 = rsqrtf(fmaxf(n0, 1e-24f));
        const float i1 = rsqrtf(fmaxf(n1, 1e-24f));
        const float i2 = rsqrtf(fmaxf(n2, 1e-24f));
        const float i3 = rsqrtf(fmaxf(n3, 1e-24f));

#pragma unroll
        for (int c = 0; c < Cn; c++) {
            const float f0 = v[c].x * i0, f1 = v[c].y * i1;
            const float f2 = v[c].z * i2, f3 = v[c].w * i3;
            at[c] += (f0 + f1) + (f2 + f3);
            a0[c] += (m0 * f0 + m1 * f1) + (m2 * f2 + m3 * f3);
        }
    }

    // Block reduce 33 slots; write partials (no atomics).
    __shared__ float sred[THR / 32][33];
    const int lane = tid & 31, w = tid >> 5;
#pragma unroll
    for (int c = 0; c < Cn; c++) { at[c] = wred(at[c]); a0[c] = wred(a0[c]); }
    cnt = wred(cnt);
    if (lane == 0) {
#pragma unroll
        for (int c = 0; c < Cn; c++) { sred[w][c] = at[c]; sred[w][16 + c] = a0[c]; }
        sred[w][32] = cnt;
    }
    __syncthreads();
    if (tid < 33) {
        float s = 0.f;
#pragma unroll
        for (int ww = 0; ww < THR / 32; ww++) s += sred[ww][tid];
        if (tid < 32)      g_part[z][b][tid][tile] = s;
        else if (z == 0)   g_cnt[b][tile] = s;
    }
}

// ---------------------------------------------------------------------------
// Finalize: reduce tile partials -> normalized mean-difference vectors dM.
// grid (Bn, 2), 256 threads.
// ---------------------------------------------------------------------------
__global__ void finalize_kernel() {
    const int b = blockIdx.x, z = blockIdx.y;
    const int tid = threadIdx.x;

    __shared__ float s[8][32];
    __shared__ float sc[8];
    __shared__ float red[32];
    __shared__ float scnt;
    __shared__ float smean[2][Cn];
    __shared__ float srn[2];

    {   // 256 threads = 32 slots x 8 groups of 8 tiles
        const int slot = tid & 31, g = tid >> 5;
        const float* base = &g_part[z][b][slot][0] + g * 8;
        float a = 0.f;
#pragma unroll
        for (int k = 0; k < 2; k++) {
            const float4 v = *(const float4*)(base + 4 * k);
            a += (v.x + v.y) + (v.z + v.w);
        }
        s[g][slot] = a;
    }
    if (tid < 8) {
        const float* cb = &g_cnt[b][0] + tid * 8;
        float a = 0.f;
#pragma unroll
        for (int k = 0; k < 2; k++) {
            const float4 v = *(const float4*)(cb + 4 * k);
            a += (v.x + v.y) + (v.z + v.w);
        }
        sc[tid] = a;
    }
    __syncthreads();
    if (tid < 32) {
        float a = 0.f;
#pragma unroll
        for (int g = 0; g < 8; g++) a += s[g][tid];
        red[tid] = a;
    } else if (tid == 32) {
        float a = 0.f;
#pragma unroll
        for (int g = 0; g < 8; g++) a += sc[g];
        scnt = a;
    }
    __syncthreads();
    if (tid < 2) {
        const int cls = tid;
        const float cnt0 = scnt;
        const float cnt  = cls ? ((float)HWn - cnt0) : cnt0;
        const float inv  = 1.0f / (cnt + 1e-6f);
        float nm2 = 0.f;
#pragma unroll
        for (int c = 0; c < Cn; c++) {
            const float tot = red[c], s0 = red[16 + c];
            const float sv  = cls ? (tot - s0) : s0;
            const float m   = sv * inv;
            smean[cls][c] = m;
            nm2 = fmaf(m, m, nm2);
        }
        srn[cls] = 1.0f / fmaxf(sqrtf(nm2), 1e-8f);
    }
    __syncthreads();
    if (tid < Cn) {
        g_dm[z][b][tid] = smean[0][tid] * srn[0] - smean[1][tid] * srn[1];
    }
}

// ---------------------------------------------------------------------------
// Pass 3: cd = dot(v, dM) * rsqrt(||v||^2); pcsim = exp(+-cd); MSE.
// grid (T3, Bn); 4 px/thread, float4 loads, channels streamed.
// ---------------------------------------------------------------------------
__global__ void __launch_bounds__(THR, 10)
pass3_kernel(const float* __restrict__ S, const float* __restrict__ T,
             const int* __restrict__ TW, float* __restrict__ out) {
    const int tile = blockIdx.x, b = blockIdx.y;
    const int tid  = threadIdx.x;
    const int is32 = sniff_is32(TW, tid);

    __shared__ float sdM[2][Cn];
    __shared__ unsigned int slast;
    if (tid < 32) {
        const int z = tid >> 4, c = tid & 15;
        sdM[z][c] = g_dm[z][b][c];
    }
    __syncthreads();

    const float* Sb  = S + ((size_t)b << 20);
    const float* Tb  = T + ((size_t)b << 20);
    const int*   twb = TW + (is32 ? ((size_t)b << 16) : ((size_t)b << 17));

    const int p = tile * PPB3 + tid * 4;
    int c0, c1, c2, c3;
    load_cls4(twb, p, is32, c0, c1, c2, c3);
    const float s0 = (c0 == 0) ? 1.f : -1.f;
    const float s1 = (c1 == 0) ? 1.f : -1.f;
    const float s2 = (c2 == 0) ? 1.f : -1.f;
    const float s3 = (c3 == 0) ? 1.f : -1.f;

    float pcS0, pcS1, pcS2, pcS3;
    {   // ---- S ----
        float n0 = 0.f, n1 = 0.f, n2 = 0.f, n3 = 0.f;
        float d0 = 0.f, d1 = 0.f, d2 = 0.f, d3 = 0.f;
#pragma unroll
        for (int c = 0; c < Cn; c++) {
            const float4 v = ldcs4(Sb + ((size_t)c << 16) + p);
            const float m = sdM[0][c];
            n0 = fmaf(v.x, v.x, n0); n1 = fmaf(v.y, v.y, n1);
            n2 = fmaf(v.z, v.z, n2); n3 = fmaf(v.w, v.w, n3);
            d0 = fmaf(v.x, m, d0); d1 = fmaf(v.y, m, d1);
            d2 = fmaf(v.z, m, d2); d3 = fmaf(v.w, m, d3);
        }
        pcS0 = __expf(s0 * d0 * rsqrtf(fmaxf(n0, 1e-24f)));
        pcS1 = __expf(s1 * d1 * rsqrtf(fmaxf(n1, 1e-24f)));
        pcS2 = __expf(s2 * d2 * rsqrtf(fmaxf(n2, 1e-24f)));
        pcS3 = __expf(s3 * d3 * rsqrtf(fmaxf(n3, 1e-24f)));
    }
    float acc;
    {   // ---- T ----
        float n0 = 0.f, n1 = 0.f, n2 = 0.f, n3 = 0.f;
        float d0 = 0.f, d1 = 0.f, d2 = 0.f, d3 = 0.f;
#pragma unroll
        for (int c = 0; c < Cn; c++) {
            const float4 v = ldcs4(Tb + ((size_t)c << 16) + p);
            const float m = sdM[1][c];
            n0 = fmaf(v.x, v.x, n0); n1 = fmaf(v.y, v.y, n1);
            n2 = fmaf(v.z, v.z, n2); n3 = fmaf(v.w, v.w, n3);
            d0 = fmaf(v.x, m, d0); d1 = fmaf(v.y, m, d1);
            d2 = fmaf(v.z, m, d2); d3 = fmaf(v.w, m, d3);
        }
        const float e0 = pcS0 - __expf(s0 * d0 * rsqrtf(fmaxf(n0, 1e-24f)));
        const float e1 = pcS1 - __expf(s1 * d1 * rsqrtf(fmaxf(n1, 1e-24f)));
        const float e2 = pcS2 - __expf(s2 * d2 * rsqrtf(fmaxf(n2, 1e-24f)));
        const float e3 = pcS3 - __expf(s3 * d3 * rsqrtf(fmaxf(n3, 1e-24f)));
        acc = fmaf(e0, e0, e1 * e1) + fmaf(e2, e2, e3 * e3);
    }

    // Block reduce MSE partial, then last-block final reduction.
    __shared__ float smse[THR / 32];
    acc = wred(acc);
    const int lane = tid & 31, w = tid >> 5;
    if (lane == 0) smse[w] = acc;
    __syncthreads();
    const int gid = b * T3 + tile;
    if (tid == 0) {
        float sv = 0.f;
#pragma unroll
        for (int ww = 0; ww < THR / 32; ww++) sv += smse[ww];
        g_msep[gid] = sv;
        __threadfence();
        const unsigned int old = atomicAdd(&g_done, 1u);
        slast = (old == (unsigned int)(Bn * T3 - 1)) ? 1u : 0u;
    }
    __syncthreads();

    if (slast) {
        volatile float* mp = &g_msep[0];
        double d = 0.0;
#pragma unroll
        for (int k = 0; k < (Bn * T3) / THR; k++)
            d += (double)mp[tid * ((Bn * T3) / THR) + k];
        d = wredd(d);
        __shared__ double sd[THR / 32];
        if (lane == 0) sd[w] = d;
        __syncthreads();
        if (tid == 0) {
            double tot = 0.0;
#pragma unroll
            for (int ww = 0; ww < THR / 32; ww++) tot += sd[ww];
            out[0] = (float)(tot * (1.0 / ((double)Bn * (double)HWn)));
            g_done = 0;   // reset for next graph replay
        }
    }
}

extern "C" void kernel_launch(void* const* d_in, const int* in_sizes, int n_in,
                              void* d_out, int out_size) {
    const float* S  = (const float*)d_in[0];
    const float* T  = (const float*)d_in[1];
    const int*   TW = (const int*)d_in[2];
    float* out = (float*)d_out;

    dim3 g1(T1, Bn, 2);
    pass1_kernel<<<g1, THR>>>(S, T, TW);
    dim3 gf(Bn, 2);
    finalize_kernel<<<gf, 256>>>();
    dim3 g3(T3, Bn);
    pass3_kernel<<<g3, THR>>>(S, T, TW, out);
}